// round 5
// baseline (speedup 1.0000x reference)
#include <cuda_runtime.h>

// Fixed problem shape (GNNReachabilityNet): N=100000 nodes, E=1600000 edges, G=64 graphs.
#define NMAX  100352
#define GMAX  64

__device__ float    g_alpha[NMAX];   // alpha = x.p2
__device__ float2   g_bg[NMAX];      // (beta = x.q2, gamma = x.p1)
__device__ float    g_delta[NMAX];   // delta = x.q1
__device__ float2   g_agg[NMAX];     // (sum alpha over incoming, deg)
__device__ float    g_w[NMAX];       // w[u] = beta[u] + s[u]
__device__ float    g_aggs[NMAX];    // sum of w[src] over incoming
__device__ unsigned g_outmax[GMAX];  // order-encoded float max
__device__ unsigned          g_cnt  = 0;
__device__ volatile unsigned g_gen  = 0;
__device__ unsigned          g_done = 0;

__device__ __forceinline__ unsigned enc_f(float f) {
    unsigned u = __float_as_uint(f);
    return (u & 0x80000000u) ? ~u : (u | 0x80000000u);
}
__device__ __forceinline__ float dec_f(unsigned e) {
    return (e & 0x80000000u) ? __uint_as_float(e ^ 0x80000000u) : __uint_as_float(~e);
}
#define ENC_NEG_INF 0x007FFFFFu

// Sense-reversing grid barrier; grid sized for guaranteed co-residency.
__device__ __forceinline__ void grid_bar(unsigned nb) {
    __syncthreads();
    if (threadIdx.x == 0) {
        __threadfence();
        unsigned gen = g_gen;
        if (atomicAdd(&g_cnt, 1u) == nb - 1u) {
            g_cnt = 0u;
            __threadfence();
            g_gen = gen + 1u;
        } else {
            while (g_gen == gen) __nanosleep(32);
        }
        __threadfence();
    }
    __syncthreads();
}

__global__ void __launch_bounds__(256, 6) k_main(
    const float* __restrict__ x, const void* __restrict__ ei,
    const void* __restrict__ batch,
    const float* __restrict__ Wv,  const float* __restrict__ bv,
    const float* __restrict__ We1, const float* __restrict__ be1,
    const float* __restrict__ Wx,  const float* __restrict__ bx,
    const float* __restrict__ We2, const float* __restrict__ be2,
    const float* __restrict__ Wo,  const float* __restrict__ bo,
    float* out, int n, int E, int out_n)
{
    __shared__ union {
        struct {  // fold scratch (reused as sx afterward)
            float wev[64], wfv[64];
            float uf[128], ue[128];
            float taf[64], tae[64], tbf[64], tbe[64];
        } f;
        float sx[256 * 11];
    } sh;
    __shared__ float sp1[11], sq1[11], sp2[11], sq2[11];
    __shared__ float s_ps, s_s0, s_qb, s_bo;
    __shared__ unsigned smax[GMAX];
    __shared__ int s_flag, s_done;

    const int tid = threadIdx.x, bid = blockIdx.x, nb = gridDim.x;
    const int gthreads = nb * 256;

    // dtype detect: int64 little-endian nonneg < 2^31 => odd 32-bit words all 0.
    if (tid == 0) {
        const unsigned* w = (const unsigned*)ei;
        int nz = 0;
#pragma unroll
        for (int i = 0; i < 64; i++) nz += (w[2 * i + 1] != 0u);
        s_flag = (nz == 0);
        if (bid == 0) g_done = 0u;
    }
    if (bid == 0 && tid < GMAX) g_outmax[tid] = ENC_NEG_INF;

    // ======== Phase 0: redundant per-block weight fold (matrix-vector) =====
    // wev = We2[0:64]@Wo, wfv = We2[64:128]@Wo
    if (tid < 64) {
        float a = 0.f, b = 0.f;
        for (int o = 0; o < 64; o++) {
            float wo = Wo[o];
            a += We2[tid * 64 + o]        * wo;
            b += We2[(64 + tid) * 64 + o] * wo;
        }
        sh.f.wev[tid] = a; sh.f.wfv[tid] = b;
    }
    __syncthreads();
    // uf = Wx@wfv, ue = Wx@wev  (128-vecs)
    if (tid < 128) {
        float a = 0.f, b = 0.f;
        for (int o = 0; o < 64; o++) {
            float wx = Wx[tid * 64 + o];
            a += wx * sh.f.wfv[o];
            b += wx * sh.f.wev[o];
        }
        sh.f.uf[tid] = a; sh.f.ue[tid] = b;
    }
    __syncthreads();
    // t vectors: taf = Wa@uf, tae = Wa@ue, tbf = Wb@uf, tbe = Wb@ue
    {
        int k = tid & 63, q = tid >> 6;
        const float* row = We1 + ((q < 2 ? k : 64 + k) * 128);
        const float* u = (q & 1) ? sh.f.ue : sh.f.uf;
        float a = 0.f;
        for (int m = 0; m < 128; m++) a += row[m] * u[m];
        if (q == 0) sh.f.taf[k] = a;
        else if (q == 1) sh.f.tae[k] = a;
        else if (q == 2) sh.f.tbf[k] = a;
        else sh.f.tbe[k] = a;
    }
    __syncthreads();
    // p/q 11-vectors + Pc/Pd corrections (We1 rows 128..131 dotted with uf/ue)
    if (tid < 44) {
        int i = tid % 11, gq = tid / 11;  // gq: 0=p1,1=q1,2=p2,3=q2
        const float* tv = (gq == 0) ? sh.f.taf : (gq == 1) ? sh.f.tae
                        : (gq == 2) ? sh.f.tbf : sh.f.tbe;
        float a = 0.f;
        for (int k = 0; k < 64; k++) a += Wv[i * 64 + k] * tv[k];
        if (i >= 9) {
            int row = (gq < 2 ? 128 : 130) + (i - 9);
            const float* u = (gq & 1) ? sh.f.ue : sh.f.uf;
            const float* r = We1 + row * 128;
            float c = 0.f;
            for (int m = 0; m < 128; m++) c += r[m] * u[m];
            a += c;
        }
        if (gq == 0) sp1[i] = a;
        else if (gq == 1) sq1[i] = a;
        else if (gq == 2) sp2[i] = a;
        else sq2[i] = a;
    }
    if (tid == 64) {
        // scalars: s0 = bx.wfv; t0 = bx.wev; ps = be1.uf + bv.(taf+tbf) + s0;
        //          qs = be1.ue + bv.(tae+tbe) + t0; b2 = be2.Wo + bo
        float s0 = 0.f, t0 = 0.f, b2 = 0.f;
        for (int o = 0; o < 64; o++) {
            s0 += bx[o]  * sh.f.wfv[o];
            t0 += bx[o]  * sh.f.wev[o];
            b2 += be2[o] * Wo[o];
        }
        float ps = s0, qs = t0;
        for (int m = 0; m < 128; m++) {
            ps += be1[m] * sh.f.uf[m];
            qs += be1[m] * sh.f.ue[m];
        }
        for (int k = 0; k < 64; k++) {
            ps += bv[k] * (sh.f.taf[k] + sh.f.tbf[k]);
            qs += bv[k] * (sh.f.tae[k] + sh.f.tbe[k]);
        }
        s_ps = ps; s_s0 = s0;
        s_qb = qs + b2 + bo[0];
        s_bo = bo[0];
    }
    __syncthreads();
    const bool f64 = (s_flag != 0);

    // ======== Phase 1: dots + zero accumulators ============================
    int ntiles = (n + 255) >> 8;
    for (int tile = bid; tile < ntiles; tile += nb) {
        int base = tile * 2816;
        int lim = n * 11 - base;
        __syncthreads();
        if (lim >= 2816) {
            const float4* xv = (const float4*)(x + base);
            float4* s4 = (float4*)sh.sx;
            s4[tid]       = xv[tid];
            s4[tid + 256] = xv[tid + 256];
            if (tid + 512 < 704) s4[tid + 512] = xv[tid + 512];
        } else {
            for (int j = tid; j < 2816; j += 256)
                sh.sx[j] = (j < lim) ? x[base + j] : 0.f;
        }
        __syncthreads();
        int v = tile * 256 + tid;
        if (v < n) {
            float a = 0.f, b = 0.f, g = 0.f, d = 0.f;
#pragma unroll
            for (int i = 0; i < 11; i++) {
                float xv = sh.sx[tid * 11 + i];
                a += xv * sp2[i]; b += xv * sq2[i];
                g += xv * sp1[i]; d += xv * sq1[i];
            }
            g_alpha[v] = a;
            g_bg[v]    = make_float2(b, g);
            g_delta[v] = d;
            g_agg[v]   = make_float2(0.f, 0.f);
            g_aggs[v]  = 0.f;
        }
    }
    grid_bar(nb);

    // ======== Phase 2: edge pass 1 (4 edges/thread) ========================
    {
        int E4 = (E >> 2);
        bool vec_ok = ((E & 3) == 0);   // alignment of the dst half
        if (vec_ok) {
            for (int gi = bid * 256 + tid; gi < E4; gi += gthreads) {
                int e = gi << 2;
                int4 s4, d4;
                if (f64) {
                    const long long* p = (const long long*)ei;
                    longlong2 sa = *(const longlong2*)(p + e);
                    longlong2 sb = *(const longlong2*)(p + e + 2);
                    longlong2 da = *(const longlong2*)(p + E + e);
                    longlong2 db = *(const longlong2*)(p + E + e + 2);
                    s4 = make_int4((int)sa.x, (int)sa.y, (int)sb.x, (int)sb.y);
                    d4 = make_int4((int)da.x, (int)da.y, (int)db.x, (int)db.y);
                } else {
                    const int* p = (const int*)ei;
                    s4 = *(const int4*)(p + e);
                    d4 = *(const int4*)(p + E + e);
                }
                float a0 = __ldg(&g_alpha[s4.x]);
                float a1 = __ldg(&g_alpha[s4.y]);
                float a2 = __ldg(&g_alpha[s4.z]);
                float a3 = __ldg(&g_alpha[s4.w]);
                atomicAdd(&g_agg[d4.x], make_float2(a0, 1.f));
                atomicAdd(&g_agg[d4.y], make_float2(a1, 1.f));
                atomicAdd(&g_agg[d4.z], make_float2(a2, 1.f));
                atomicAdd(&g_agg[d4.w], make_float2(a3, 1.f));
            }
        }
        int start = vec_ok ? (E4 << 2) : 0;
        for (int e = start + bid * 256 + tid; e < E; e += gthreads) {
            int s, d;
            if (f64) {
                const long long* p = (const long long*)ei;
                s = (int)p[e]; d = (int)p[E + e];
            } else {
                const int* p = (const int*)ei;
                s = p[e]; d = p[E + e];
            }
            atomicAdd(&g_agg[d], make_float2(__ldg(&g_alpha[s]), 1.f));
        }
    }
    grid_bar(nb);

    // ======== Phase 3: nodes — w = beta + s ================================
    {
        float ps_ = s_ps, s0_ = s_s0;
        for (int v = bid * 256 + tid; v < n; v += gthreads) {
            float2 ag = __ldcg(&g_agg[v]);       // atomic-written: bypass L1
            float2 bg = g_bg[v];
            float s = (ag.y > 0.f) ? (bg.y + (1.f / ag.y) * ag.x + ps_) : s0_;
            g_w[v] = bg.x + s;
        }
    }
    grid_bar(nb);

    // ======== Phase 4: edge pass 2 (4 edges/thread) ========================
    {
        int E4 = (E >> 2);
        bool vec_ok = ((E & 3) == 0);
        if (vec_ok) {
            for (int gi = bid * 256 + tid; gi < E4; gi += gthreads) {
                int e = gi << 2;
                int4 s4, d4;
                if (f64) {
                    const long long* p = (const long long*)ei;
                    longlong2 sa = *(const longlong2*)(p + e);
                    longlong2 sb = *(const longlong2*)(p + e + 2);
                    longlong2 da = *(const longlong2*)(p + E + e);
                    longlong2 db = *(const longlong2*)(p + E + e + 2);
                    s4 = make_int4((int)sa.x, (int)sa.y, (int)sb.x, (int)sb.y);
                    d4 = make_int4((int)da.x, (int)da.y, (int)db.x, (int)db.y);
                } else {
                    const int* p = (const int*)ei;
                    s4 = *(const int4*)(p + e);
                    d4 = *(const int4*)(p + E + e);
                }
                float w0 = __ldg(&g_w[s4.x]);
                float w1 = __ldg(&g_w[s4.y]);
                float w2 = __ldg(&g_w[s4.z]);
                float w3 = __ldg(&g_w[s4.w]);
                atomicAdd(&g_aggs[d4.x], w0);
                atomicAdd(&g_aggs[d4.y], w1);
                atomicAdd(&g_aggs[d4.z], w2);
                atomicAdd(&g_aggs[d4.w], w3);
            }
        }
        int start = vec_ok ? (E4 << 2) : 0;
        for (int e = start + bid * 256 + tid; e < E; e += gthreads) {
            int s, d;
            if (f64) {
                const long long* p = (const long long*)ei;
                s = (int)p[e]; d = (int)p[E + e];
            } else {
                const int* p = (const int*)ei;
                s = p[e]; d = p[E + e];
            }
            atomicAdd(&g_aggs[d], __ldg(&g_w[s]));
        }
    }
    grid_bar(nb);

    // ======== Phase 5: final node_out + segment max + writeout =============
    if (tid < GMAX) smax[tid] = ENC_NEG_INF;
    __syncthreads();
    {
        float qb = s_qb, bo_ = s_bo;
        for (int v = bid * 256 + tid; v < n; v += gthreads) {
            float deg = __ldcg(&g_agg[v]).y;
            float no = (deg > 0.f)
                     ? (g_delta[v] + qb + (1.f / deg) * __ldcg(&g_aggs[v]))
                     : bo_;
            int g = f64 ? (int)((const long long*)batch)[v]
                        : ((const int*)batch)[v];
            atomicMax(&smax[g], enc_f(no));
        }
    }
    __syncthreads();
    if (tid < GMAX && smax[tid] != ENC_NEG_INF)
        atomicMax(&g_outmax[tid], smax[tid]);
    __syncthreads();
    if (tid == 0) {
        __threadfence();
        s_done = (atomicAdd(&g_done, 1u) == (unsigned)nb - 1u);
    }
    __syncthreads();
    if (s_done && tid < GMAX && tid < out_n)
        out[tid] = dec_f(__ldcg(&g_outmax[tid]));
}

extern "C" void kernel_launch(void* const* d_in, const int* in_sizes, int n_in,
                              void* d_out, int out_size) {
    const float* x     = (const float*)d_in[0];
    const void*  ei    = d_in[1];
    const void*  batch = d_in[2];
    const float* Wv  = (const float*)d_in[3];
    const float* bv  = (const float*)d_in[4];
    const float* We1 = (const float*)d_in[5];
    const float* be1 = (const float*)d_in[6];
    const float* Wx  = (const float*)d_in[7];
    const float* bx  = (const float*)d_in[8];
    const float* We2 = (const float*)d_in[9];
    const float* be2 = (const float*)d_in[10];
    const float* Wo  = (const float*)d_in[11];
    const float* bo  = (const float*)d_in[12];
    float* out = (float*)d_out;

    int n = in_sizes[0] / 11;   // 100000
    int E = in_sizes[1] / 2;    // 1600000
    if (n > NMAX) n = NMAX;

    int sms = 148;
    cudaDeviceGetAttribute(&sms, cudaDevAttrMultiProcessorCount, 0);
    int bpm = 0;
    cudaOccupancyMaxActiveBlocksPerMultiprocessor(&bpm, k_main, 256, 0);
    if (bpm < 1) bpm = 1;
    if (bpm > 6) bpm = 6;
    int grid = sms * bpm;

    k_main<<<grid, 256>>>(x, ei, batch, Wv, bv, We1, be1, Wx, bx,
                          We2, be2, Wo, bo, out, n, E, out_size);
}

// round 6
// speedup vs baseline: 2.7527x; 2.7527x over previous
#include <cuda_runtime.h>

// Fixed problem shape (GNNReachabilityNet): N=100000 nodes, E=1600000 edges, G=64 graphs.
#define NMAX  100352
#define GMAX  64

struct Params {
    float p1[11], q1[11], p2[11], q2[11];
    float ps, qs, s0, b2, bo;
};

__device__ Params   gP;
__device__ float    g_alpha[NMAX];   // alpha = x.p2
__device__ float2   g_bg[NMAX];      // (beta = x.q2, gamma = x.p1)
__device__ float    g_delta[NMAX];   // delta = x.q1
__device__ float2   g_agg[NMAX];     // (sum alpha over incoming, deg)
__device__ float    g_w[NMAX];       // w[u] = beta[u] + s[u]
__device__ float    g_aggs[NMAX];    // sum of w[src] over incoming
__device__ unsigned g_outmax[GMAX];  // order-encoded float max
__device__ unsigned g_done = 0;
__device__ int      g_flag;          // 1 = int64 indices, 0 = int32

__device__ __forceinline__ unsigned enc_f(float f) {
    unsigned u = __float_as_uint(f);
    return (u & 0x80000000u) ? ~u : (u | 0x80000000u);
}
__device__ __forceinline__ float dec_f(unsigned e) {
    return (e & 0x80000000u) ? __uint_as_float(e ^ 0x80000000u) : __uint_as_float(~e);
}
#define ENC_NEG_INF 0x007FFFFFu

// ---------------------------------------------------------------------------
// K1: single-block weight fold via right-to-left matrix-vector products
// (~60k MACs). Also: dtype detect, init g_outmax / g_done.
// ---------------------------------------------------------------------------
__global__ void k_fold(const float* __restrict__ Wv,  const float* __restrict__ bv,
                       const float* __restrict__ We1, const float* __restrict__ be1,
                       const float* __restrict__ Wx,  const float* __restrict__ bx,
                       const float* __restrict__ We2, const float* __restrict__ be2,
                       const float* __restrict__ Wo,  const float* __restrict__ bo,
                       const unsigned* __restrict__ ei_words) {
    __shared__ float wev[64], wfv[64];
    __shared__ float uf[128], ue[128];
    __shared__ float taf[64], tae[64], tbf[64], tbe[64];
    const int tid = threadIdx.x;  // 256 threads

    if (tid == 0) {
        int nz = 0;
#pragma unroll
        for (int i = 0; i < 64; i++) nz += (ei_words[2 * i + 1] != 0u);
        g_flag = (nz == 0);
        g_done = 0u;
    }
    if (tid < GMAX) g_outmax[tid] = ENC_NEG_INF;

    // wev = We2[0:64]@Wo, wfv = We2[64:128]@Wo
    if (tid < 64) {
        float a = 0.f, b = 0.f;
        for (int o = 0; o < 64; o++) {
            float wo = Wo[o];
            a += We2[tid * 64 + o]        * wo;
            b += We2[(64 + tid) * 64 + o] * wo;
        }
        wev[tid] = a; wfv[tid] = b;
    }
    __syncthreads();
    // uf = Wx@wfv, ue = Wx@wev
    if (tid < 128) {
        float a = 0.f, b = 0.f;
        for (int o = 0; o < 64; o++) {
            float wx = Wx[tid * 64 + o];
            a += wx * wfv[o];
            b += wx * wev[o];
        }
        uf[tid] = a; ue[tid] = b;
    }
    __syncthreads();
    // taf = Wa@uf, tae = Wa@ue, tbf = Wb@uf, tbe = Wb@ue
    {
        int k = tid & 63, q = tid >> 6;
        const float* row = We1 + ((q < 2 ? k : 64 + k) * 128);
        const float* u = (q & 1) ? ue : uf;
        float a = 0.f;
        for (int m = 0; m < 128; m++) a += row[m] * u[m];
        if (q == 0) taf[k] = a;
        else if (q == 1) tae[k] = a;
        else if (q == 2) tbf[k] = a;
        else tbe[k] = a;
    }
    __syncthreads();
    // p/q 11-vectors (+ rows 128..131 corrections for x cols 9,10)
    if (tid < 44) {
        int i = tid % 11, gq = tid / 11;  // 0=p1,1=q1,2=p2,3=q2
        const float* tv = (gq == 0) ? taf : (gq == 1) ? tae : (gq == 2) ? tbf : tbe;
        float a = 0.f;
        for (int k = 0; k < 64; k++) a += Wv[i * 64 + k] * tv[k];
        if (i >= 9) {
            int row = (gq < 2 ? 128 : 130) + (i - 9);
            const float* u = (gq & 1) ? ue : uf;
            const float* r = We1 + row * 128;
            float c = 0.f;
            for (int m = 0; m < 128; m++) c += r[m] * u[m];
            a += c;
        }
        if (gq == 0) gP.p1[i] = a;
        else if (gq == 1) gP.q1[i] = a;
        else if (gq == 2) gP.p2[i] = a;
        else gP.q2[i] = a;
    }
    if (tid == 64) {
        float s0 = 0.f, t0 = 0.f, b2 = 0.f;
        for (int o = 0; o < 64; o++) {
            s0 += bx[o]  * wfv[o];
            t0 += bx[o]  * wev[o];
            b2 += be2[o] * Wo[o];
        }
        float ps = s0, qs = t0;
        for (int m = 0; m < 128; m++) {
            ps += be1[m] * uf[m];
            qs += be1[m] * ue[m];
        }
        for (int k = 0; k < 64; k++) {
            ps += bv[k] * (taf[k] + tbf[k]);
            qs += bv[k] * (tae[k] + tbe[k]);
        }
        gP.ps = ps; gP.qs = qs; gP.s0 = s0;
        gP.b2 = b2 + bo[0]; gP.bo = bo[0];
    }
}

// ---------------------------------------------------------------------------
// K2: per-node 11-dim dots (x staged via smem float4); zero accumulators.
// ---------------------------------------------------------------------------
__global__ void __launch_bounds__(256) k_dots(const float* __restrict__ x, int n) {
    __shared__ float sx[256 * 11];
    __shared__ float sp1[11], sq1[11], sp2[11], sq2[11];
    int t = threadIdx.x;
    if (t < 11) {
        sp1[t] = gP.p1[t]; sq1[t] = gP.q1[t];
        sp2[t] = gP.p2[t]; sq2[t] = gP.q2[t];
    }
    int base = blockIdx.x * 2816;
    int lim = n * 11 - base;
    if (lim >= 2816) {
        const float4* xv = (const float4*)(x + base);
        float4* s4 = (float4*)sx;
        s4[t]       = xv[t];
        s4[t + 256] = xv[t + 256];
        if (t + 512 < 704) s4[t + 512] = xv[t + 512];
    } else {
        for (int j = t; j < 2816; j += 256)
            sx[j] = (j < lim) ? x[base + j] : 0.f;
    }
    __syncthreads();
    int v = blockIdx.x * 256 + t;
    if (v < n) {
        float a = 0.f, b = 0.f, g = 0.f, d = 0.f;
#pragma unroll
        for (int i = 0; i < 11; i++) {
            float xv = sx[t * 11 + i];
            a += xv * sp2[i]; b += xv * sq2[i];
            g += xv * sp1[i]; d += xv * sq1[i];
        }
        g_alpha[v] = a;
        g_bg[v]    = make_float2(b, g);
        g_delta[v] = d;
        g_agg[v]   = make_float2(0.f, 0.f);
        g_aggs[v]  = 0.f;
    }
}

// ---------------------------------------------------------------------------
// Index batch loader: 8 src + 8 dst indices with wide loads.
// ---------------------------------------------------------------------------
__device__ __forceinline__ void load8(const void* ei, int E, int e, bool f64,
                                      int* s, int* d) {
    if (f64) {
        const long long* p = (const long long*)ei;
        const longlong2* ps = (const longlong2*)(p + e);
        const longlong2* pd = (const longlong2*)(p + E + e);
#pragma unroll
        for (int j = 0; j < 4; j++) {
            longlong2 a = ps[j]; s[2 * j] = (int)a.x; s[2 * j + 1] = (int)a.y;
        }
#pragma unroll
        for (int j = 0; j < 4; j++) {
            longlong2 a = pd[j]; d[2 * j] = (int)a.x; d[2 * j + 1] = (int)a.y;
        }
    } else {
        const int* p = (const int*)ei;
        const int4* ps = (const int4*)(p + e);
        const int4* pd = (const int4*)(p + E + e);
#pragma unroll
        for (int j = 0; j < 2; j++) {
            int4 a = ps[j];
            s[4 * j] = a.x; s[4 * j + 1] = a.y; s[4 * j + 2] = a.z; s[4 * j + 3] = a.w;
        }
#pragma unroll
        for (int j = 0; j < 2; j++) {
            int4 a = pd[j];
            d[4 * j] = a.x; d[4 * j + 1] = a.y; d[4 * j + 2] = a.z; d[4 * j + 3] = a.w;
        }
    }
}

// ---------------------------------------------------------------------------
// K3: edge pass 1 — 8 edges/thread: batch index loads, 8 gathers, 8 REDs.
// ---------------------------------------------------------------------------
__global__ void __launch_bounds__(256) k_edge1(const void* __restrict__ ei, int E) {
    const bool f64 = (g_flag != 0);
    const bool vec_ok = f64 ? ((E & 1) == 0) : ((E & 3) == 0);
    int i = blockIdx.x * 256 + threadIdx.x;
    int E8 = vec_ok ? (E >> 3) : 0;
    if (i < E8) {
        int s[8], d[8];
        load8(ei, E, i << 3, f64, s, d);
        float a[8];
#pragma unroll
        for (int j = 0; j < 8; j++) a[j] = __ldg(&g_alpha[s[j]]);
#pragma unroll
        for (int j = 0; j < 8; j++)
            atomicAdd(&g_agg[d[j]], make_float2(a[j], 1.f));
    }
    int tail = E - (E8 << 3);
    if (i < tail) {
        int e = (E8 << 3) + i;
        int s, d;
        if (f64) {
            const long long* p = (const long long*)ei;
            s = (int)p[e]; d = (int)p[E + e];
        } else {
            const int* p = (const int*)ei;
            s = p[e]; d = p[E + e];
        }
        atomicAdd(&g_agg[d], make_float2(__ldg(&g_alpha[s]), 1.f));
    }
}

// ---------------------------------------------------------------------------
// K4: per-node w = beta + s, 2 nodes/thread with float4 loads.
// ---------------------------------------------------------------------------
__global__ void __launch_bounds__(256) k_nodes(int n) {
    int i = blockIdx.x * 256 + threadIdx.x;
    int half = n >> 1;
    float ps = gP.ps, s0 = gP.s0;
    if (i < half) {
        float4 ag = ((const float4*)g_agg)[i];  // (a0,deg0,a1,deg1)
        float4 bg = ((const float4*)g_bg)[i];   // (b0,g0,b1,g1)
        float w0 = (ag.y > 0.f) ? (bg.x + bg.y + (1.f / ag.y) * ag.x + ps)
                                : (bg.x + s0);
        float w1 = (ag.w > 0.f) ? (bg.z + bg.w + (1.f / ag.w) * ag.z + ps)
                                : (bg.z + s0);
        ((float2*)g_w)[i] = make_float2(w0, w1);
    }
    // odd-n tail
    if (i == 0 && (n & 1)) {
        int v = n - 1;
        float2 ag = g_agg[v];
        float2 bg = g_bg[v];
        g_w[v] = (ag.y > 0.f) ? (bg.x + bg.y + (1.f / ag.y) * ag.x + ps)
                              : (bg.x + s0);
    }
}

// ---------------------------------------------------------------------------
// K5: edge pass 2 — 8 edges/thread, scalar REDs: aggs[dst] += w[src].
// ---------------------------------------------------------------------------
__global__ void __launch_bounds__(256) k_edge2(const void* __restrict__ ei, int E) {
    const bool f64 = (g_flag != 0);
    const bool vec_ok = f64 ? ((E & 1) == 0) : ((E & 3) == 0);
    int i = blockIdx.x * 256 + threadIdx.x;
    int E8 = vec_ok ? (E >> 3) : 0;
    if (i < E8) {
        int s[8], d[8];
        load8(ei, E, i << 3, f64, s, d);
        float w[8];
#pragma unroll
        for (int j = 0; j < 8; j++) w[j] = __ldg(&g_w[s[j]]);
#pragma unroll
        for (int j = 0; j < 8; j++) atomicAdd(&g_aggs[d[j]], w[j]);
    }
    int tail = E - (E8 << 3);
    if (i < tail) {
        int e = (E8 << 3) + i;
        int s, d;
        if (f64) {
            const long long* p = (const long long*)ei;
            s = (int)p[e]; d = (int)p[E + e];
        } else {
            const int* p = (const int*)ei;
            s = p[e]; d = p[E + e];
        }
        atomicAdd(&g_aggs[d], __ldg(&g_w[s]));
    }
}

// ---------------------------------------------------------------------------
// K6: node_out + segment max (2 nodes/thread) + last-block writeout.
// ---------------------------------------------------------------------------
__global__ void __launch_bounds__(256) k_final(const void* __restrict__ batch,
                                               float* out, int n, int out_n) {
    __shared__ unsigned smax[GMAX];
    __shared__ int s_done;
    int t = threadIdx.x;
    if (t < GMAX) smax[t] = ENC_NEG_INF;
    __syncthreads();

    const bool f64 = (g_flag != 0);
    float qb = gP.qs + gP.b2, bo_ = gP.bo;
    int i = blockIdx.x * 256 + t;
    int half = (n + 1) >> 1;
    if (i < half) {
        int v1 = 2 * i + 1;
        float4 ag = ((const float4*)g_agg)[i];
        float2 dl = ((const float2*)g_delta)[i];
        float2 as = ((const float2*)g_aggs)[i];
        float no0 = (ag.y > 0.f) ? (dl.x + qb + (1.f / ag.y) * as.x) : bo_;
        int g0, g1 = 0;
        if (f64) {
            const long long* b = (const long long*)batch;
            g0 = (int)b[2 * i];
            if (v1 < n) g1 = (int)b[v1];
        } else {
            const int* b = (const int*)batch;
            g0 = b[2 * i];
            if (v1 < n) g1 = b[v1];
        }
        atomicMax(&smax[g0], enc_f(no0));
        if (v1 < n) {
            float no1 = (ag.w > 0.f) ? (dl.y + qb + (1.f / ag.w) * as.y) : bo_;
            atomicMax(&smax[g1], enc_f(no1));
        }
    }
    __syncthreads();
    if (t < GMAX && smax[t] != ENC_NEG_INF)
        atomicMax(&g_outmax[t], smax[t]);
    __syncthreads();
    if (t == 0) {
        __threadfence();
        s_done = (atomicAdd(&g_done, 1u) == gridDim.x - 1u);
    }
    __syncthreads();
    if (s_done && t < GMAX && t < out_n) {
        unsigned v = atomicAdd(&g_outmax[t], 0u);  // coherent L2 read
        out[t] = dec_f(v);
    }
}

extern "C" void kernel_launch(void* const* d_in, const int* in_sizes, int n_in,
                              void* d_out, int out_size) {
    const float* x     = (const float*)d_in[0];
    const void*  ei    = d_in[1];
    const void*  batch = d_in[2];
    const float* Wv  = (const float*)d_in[3];
    const float* bv  = (const float*)d_in[4];
    const float* We1 = (const float*)d_in[5];
    const float* be1 = (const float*)d_in[6];
    const float* Wx  = (const float*)d_in[7];
    const float* bx  = (const float*)d_in[8];
    const float* We2 = (const float*)d_in[9];
    const float* be2 = (const float*)d_in[10];
    const float* Wo  = (const float*)d_in[11];
    const float* bo  = (const float*)d_in[12];
    float* out = (float*)d_out;

    int n = in_sizes[0] / 11;   // 100000
    int E = in_sizes[1] / 2;    // 1600000
    if (n > NMAX) n = NMAX;

    const int TPB = 256;
    int nb_n  = (n + TPB - 1) / TPB;
    int nb_h  = ((n + 1) / 2 + TPB - 1) / TPB;
    int nb_e8 = ((E + 7) / 8 + TPB - 1) / TPB;
    if (nb_e8 < 1) nb_e8 = 1;

    k_fold<<<1, 256>>>(Wv, bv, We1, be1, Wx, bx, We2, be2, Wo, bo,
                       (const unsigned*)ei);
    k_dots<<<nb_n, TPB>>>(x, n);
    k_edge1<<<nb_e8, TPB>>>(ei, E);
    k_nodes<<<nb_h, TPB>>>(n);
    k_edge2<<<nb_e8, TPB>>>(ei, E);
    k_final<<<nb_h, TPB>>>(batch, out, n, out_size);
}

// round 7
// speedup vs baseline: 2.9152x; 1.0590x over previous
#include <cuda_runtime.h>

// Fixed problem shape (GNNReachabilityNet): N=100000 nodes, E=1600000 edges, G=64 graphs.
#define NMAX  100352
#define GMAX  64
#define EMAXH 800000   // max edge pairs (E/2)
#define NREP  4        // accumulator replicas (atomic contention split)

struct Params {
    float p1[11], q1[11], p2[11], q2[11];
    float ps, qs, s0, b2, bo;
};

__device__ Params   gP;
__device__ float    g_alpha[NMAX];        // alpha = x.p2
__device__ float2   g_bg[NMAX];           // (beta = x.q2, gamma = x.p1)
__device__ float    g_delta[NMAX];        // delta = x.q1
__device__ float2   g_agg4[NREP][NMAX];   // replicas of (sum alpha, deg)
__device__ float    g_aggs4[NREP][NMAX];  // replicas of sum w[src]
__device__ float    g_deg[NMAX];          // combined degree (k_nodes -> k_final)
__device__ float    g_w[NMAX];            // w[u] = beta[u] + s[u]
__device__ int4     g_eidx[EMAXH];        // packed (s0,d0,s1,d1) per edge pair
__device__ unsigned g_outmax[GMAX];       // order-encoded float max
__device__ unsigned g_done = 0;
__device__ int      g_flag;               // 1 = int64 indices, 0 = int32

__device__ __forceinline__ unsigned enc_f(float f) {
    unsigned u = __float_as_uint(f);
    return (u & 0x80000000u) ? ~u : (u | 0x80000000u);
}
__device__ __forceinline__ float dec_f(unsigned e) {
    return (e & 0x80000000u) ? __uint_as_float(e ^ 0x80000000u) : __uint_as_float(~e);
}
#define ENC_NEG_INF 0x007FFFFFu

// ---------------------------------------------------------------------------
// K1: single-block weight fold via right-to-left matrix-vector products
// (~60k MACs). Also: dtype detect, init g_outmax / g_done.
// ---------------------------------------------------------------------------
__global__ void k_fold(const float* __restrict__ Wv,  const float* __restrict__ bv,
                       const float* __restrict__ We1, const float* __restrict__ be1,
                       const float* __restrict__ Wx,  const float* __restrict__ bx,
                       const float* __restrict__ We2, const float* __restrict__ be2,
                       const float* __restrict__ Wo,  const float* __restrict__ bo,
                       const unsigned* __restrict__ ei_words) {
    __shared__ float wev[64], wfv[64];
    __shared__ float uf[128], ue[128];
    __shared__ float taf[64], tae[64], tbf[64], tbe[64];
    const int tid = threadIdx.x;  // 256 threads

    if (tid == 0) {
        int nz = 0;
#pragma unroll
        for (int i = 0; i < 64; i++) nz += (ei_words[2 * i + 1] != 0u);
        g_flag = (nz == 0);
        g_done = 0u;
    }
    if (tid < GMAX) g_outmax[tid] = ENC_NEG_INF;

    if (tid < 64) {
        float a = 0.f, b = 0.f;
        for (int o = 0; o < 64; o++) {
            float wo = Wo[o];
            a += We2[tid * 64 + o]        * wo;
            b += We2[(64 + tid) * 64 + o] * wo;
        }
        wev[tid] = a; wfv[tid] = b;
    }
    __syncthreads();
    if (tid < 128) {
        float a = 0.f, b = 0.f;
        for (int o = 0; o < 64; o++) {
            float wx = Wx[tid * 64 + o];
            a += wx * wfv[o];
            b += wx * wev[o];
        }
        uf[tid] = a; ue[tid] = b;
    }
    __syncthreads();
    {
        int k = tid & 63, q = tid >> 6;
        const float* row = We1 + ((q < 2 ? k : 64 + k) * 128);
        const float* u = (q & 1) ? ue : uf;
        float a = 0.f;
        for (int m = 0; m < 128; m++) a += row[m] * u[m];
        if (q == 0) taf[k] = a;
        else if (q == 1) tae[k] = a;
        else if (q == 2) tbf[k] = a;
        else tbe[k] = a;
    }
    __syncthreads();
    if (tid < 44) {
        int i = tid % 11, gq = tid / 11;  // 0=p1,1=q1,2=p2,3=q2
        const float* tv = (gq == 0) ? taf : (gq == 1) ? tae : (gq == 2) ? tbf : tbe;
        float a = 0.f;
        for (int k = 0; k < 64; k++) a += Wv[i * 64 + k] * tv[k];
        if (i >= 9) {
            int row = (gq < 2 ? 128 : 130) + (i - 9);
            const float* u = (gq & 1) ? ue : uf;
            const float* r = We1 + row * 128;
            float c = 0.f;
            for (int m = 0; m < 128; m++) c += r[m] * u[m];
            a += c;
        }
        if (gq == 0) gP.p1[i] = a;
        else if (gq == 1) gP.q1[i] = a;
        else if (gq == 2) gP.p2[i] = a;
        else gP.q2[i] = a;
    }
    if (tid == 64) {
        float s0 = 0.f, t0 = 0.f, b2 = 0.f;
        for (int o = 0; o < 64; o++) {
            s0 += bx[o]  * wfv[o];
            t0 += bx[o]  * wev[o];
            b2 += be2[o] * Wo[o];
        }
        float ps = s0, qs = t0;
        for (int m = 0; m < 128; m++) {
            ps += be1[m] * uf[m];
            qs += be1[m] * ue[m];
        }
        for (int k = 0; k < 64; k++) {
            ps += bv[k] * (taf[k] + tbf[k]);
            qs += bv[k] * (tae[k] + tbe[k]);
        }
        gP.ps = ps; gP.qs = qs; gP.s0 = s0;
        gP.b2 = b2 + bo[0]; gP.bo = bo[0];
    }
}

// ---------------------------------------------------------------------------
// K2: per-node 11-dim dots (x staged via smem float4); zero replica accums.
// ---------------------------------------------------------------------------
__global__ void __launch_bounds__(256) k_dots(const float* __restrict__ x, int n) {
    __shared__ float sx[256 * 11];
    __shared__ float sp1[11], sq1[11], sp2[11], sq2[11];
    int t = threadIdx.x;
    if (t < 11) {
        sp1[t] = gP.p1[t]; sq1[t] = gP.q1[t];
        sp2[t] = gP.p2[t]; sq2[t] = gP.q2[t];
    }
    int base = blockIdx.x * 2816;
    int lim = n * 11 - base;
    if (lim >= 2816) {
        const float4* xv = (const float4*)(x + base);
        float4* s4 = (float4*)sx;
        s4[t]       = xv[t];
        s4[t + 256] = xv[t + 256];
        if (t + 512 < 704) s4[t + 512] = xv[t + 512];
    } else {
        for (int j = t; j < 2816; j += 256)
            sx[j] = (j < lim) ? x[base + j] : 0.f;
    }
    __syncthreads();
    int v = blockIdx.x * 256 + t;
    if (v < n) {
        float a = 0.f, b = 0.f, g = 0.f, d = 0.f;
#pragma unroll
        for (int i = 0; i < 11; i++) {
            float xv = sx[t * 11 + i];
            a += xv * sp2[i]; b += xv * sq2[i];
            g += xv * sp1[i]; d += xv * sq1[i];
        }
        g_alpha[v] = a;
        g_bg[v]    = make_float2(b, g);
        g_delta[v] = d;
#pragma unroll
        for (int r = 0; r < NREP; r++) {
            g_agg4[r][v]  = make_float2(0.f, 0.f);
            g_aggs4[r][v] = 0.f;
        }
    }
}

// ---------------------------------------------------------------------------
// K3: edge pass 1 — 2 edges/thread (R3-proven): wide index loads, write
// packed int32 pairs, gather alpha, float2 RED into replica (i & 3).
// ---------------------------------------------------------------------------
__global__ void __launch_bounds__(256) k_edge1(const void* __restrict__ ei, int E) {
    int i = blockIdx.x * 256 + threadIdx.x;
    int e0 = 2 * i;
    if (e0 >= E) return;
    const bool f64 = (g_flag != 0);
    int r = i & (NREP - 1);
    int s0, s1, d0, d1;
    bool two = (e0 + 1 < E);
    if (f64) {
        const long long* p = (const long long*)ei;
        if (two) {
            longlong2 sv = *(const longlong2*)(p + e0);
            s0 = (int)sv.x; s1 = (int)sv.y;
            if ((E & 1) == 0) {
                longlong2 dv = *(const longlong2*)(p + E + e0);
                d0 = (int)dv.x; d1 = (int)dv.y;
            } else {
                d0 = (int)p[E + e0]; d1 = (int)p[E + e0 + 1];
            }
        } else {
            s0 = (int)p[e0]; d0 = (int)p[E + e0]; s1 = s0; d1 = -1;
        }
    } else {
        const int* p = (const int*)ei;
        if (two) {
            int2 sv = *(const int2*)(p + e0);
            s0 = sv.x; s1 = sv.y;
            if ((E & 1) == 0) {
                int2 dv = *(const int2*)(p + E + e0);
                d0 = dv.x; d1 = dv.y;
            } else {
                d0 = p[E + e0]; d1 = p[E + e0 + 1];
            }
        } else {
            s0 = p[e0]; d0 = p[E + e0]; s1 = s0; d1 = -1;
        }
    }
    g_eidx[i] = make_int4(s0, d0, s1, d1);

    float a0 = __ldg(&g_alpha[s0]);
    if (d1 >= 0) {
        float a1 = __ldg(&g_alpha[s1]);
        if (d0 == d1) {
            atomicAdd(&g_agg4[r][d0], make_float2(a0 + a1, 2.f));
        } else {
            atomicAdd(&g_agg4[r][d0], make_float2(a0, 1.f));
            atomicAdd(&g_agg4[r][d1], make_float2(a1, 1.f));
        }
    } else {
        atomicAdd(&g_agg4[r][d0], make_float2(a0, 1.f));
    }
}

// ---------------------------------------------------------------------------
// K4: reduce replicas; w = beta + s; stash combined deg for k_final.
// ---------------------------------------------------------------------------
__global__ void __launch_bounds__(256) k_nodes(int n) {
    int v = blockIdx.x * 256 + threadIdx.x;
    if (v >= n) return;
    float2 a0 = g_agg4[0][v], a1 = g_agg4[1][v];
    float2 a2 = g_agg4[2][v], a3 = g_agg4[3][v];
    float sa  = (a0.x + a1.x) + (a2.x + a3.x);
    float deg = (a0.y + a1.y) + (a2.y + a3.y);
    float2 bg = g_bg[v];
    float s = (deg > 0.f) ? (bg.y + (1.f / deg) * sa + gP.ps) : gP.s0;
    g_deg[v] = deg;
    g_w[v] = bg.x + s;
}

// ---------------------------------------------------------------------------
// K5: edge pass 2 — 2 edges/thread from packed pairs; scalar RED into replica.
// ---------------------------------------------------------------------------
__global__ void __launch_bounds__(256) k_edge2(int E) {
    int i = blockIdx.x * 256 + threadIdx.x;
    if (2 * i >= E) return;
    int r = i & (NREP - 1);
    int4 p = g_eidx[i];
    float w0 = __ldg(&g_w[p.x]);
    if (p.w >= 0) {
        float w1 = __ldg(&g_w[p.z]);
        if (p.y == p.w) {
            atomicAdd(&g_aggs4[r][p.y], w0 + w1);
        } else {
            atomicAdd(&g_aggs4[r][p.y], w0);
            atomicAdd(&g_aggs4[r][p.w], w1);
        }
    } else {
        atomicAdd(&g_aggs4[r][p.y], w0);
    }
}

// ---------------------------------------------------------------------------
// K6: node_out + segment max + last-block writeout.
// ---------------------------------------------------------------------------
__global__ void __launch_bounds__(256) k_final(const void* __restrict__ batch,
                                               float* out, int n, int out_n) {
    __shared__ unsigned smax[GMAX];
    __shared__ int s_done;
    int t = threadIdx.x;
    if (t < GMAX) smax[t] = ENC_NEG_INF;
    __syncthreads();

    const bool f64 = (g_flag != 0);
    float qb = gP.qs + gP.b2, bo_ = gP.bo;
    int v = blockIdx.x * 256 + t;
    if (v < n) {
        float deg = g_deg[v];
        float no;
        if (deg > 0.f) {
            float as = (g_aggs4[0][v] + g_aggs4[1][v])
                     + (g_aggs4[2][v] + g_aggs4[3][v]);
            no = g_delta[v] + qb + (1.f / deg) * as;
        } else {
            no = bo_;
        }
        int g = f64 ? (int)((const long long*)batch)[v]
                    : ((const int*)batch)[v];
        atomicMax(&smax[g], enc_f(no));
    }
    __syncthreads();
    if (t < GMAX && smax[t] != ENC_NEG_INF)
        atomicMax(&g_outmax[t], smax[t]);
    __syncthreads();
    if (t == 0) {
        __threadfence();
        s_done = (atomicAdd(&g_done, 1u) == gridDim.x - 1u);
    }
    __syncthreads();
    if (s_done && t < GMAX && t < out_n) {
        unsigned vmax = atomicAdd(&g_outmax[t], 0u);  // coherent L2 read
        out[t] = dec_f(vmax);
    }
}

extern "C" void kernel_launch(void* const* d_in, const int* in_sizes, int n_in,
                              void* d_out, int out_size) {
    const float* x     = (const float*)d_in[0];
    const void*  ei    = d_in[1];
    const void*  batch = d_in[2];
    const float* Wv  = (const float*)d_in[3];
    const float* bv  = (const float*)d_in[4];
    const float* We1 = (const float*)d_in[5];
    const float* be1 = (const float*)d_in[6];
    const float* Wx  = (const float*)d_in[7];
    const float* bx  = (const float*)d_in[8];
    const float* We2 = (const float*)d_in[9];
    const float* be2 = (const float*)d_in[10];
    const float* Wo  = (const float*)d_in[11];
    const float* bo  = (const float*)d_in[12];
    float* out = (float*)d_out;

    int n = in_sizes[0] / 11;   // 100000
    int E = in_sizes[1] / 2;    // 1600000
    if (n > NMAX) n = NMAX;
    if (E > 2 * EMAXH) E = 2 * EMAXH;

    const int TPB = 256;
    int nb_n = (n + TPB - 1) / TPB;
    int nb_e = ((E + 1) / 2 + TPB - 1) / TPB;

    k_fold<<<1, 256>>>(Wv, bv, We1, be1, Wx, bx, We2, be2, Wo, bo,
                       (const unsigned*)ei);
    k_dots<<<nb_n, TPB>>>(x, n);
    k_edge1<<<nb_e, TPB>>>(ei, E);
    k_nodes<<<nb_n, TPB>>>(n);
    k_edge2<<<nb_e, TPB>>>(E);
    k_final<<<nb_n, TPB>>>(batch, out, n, out_size);
}

// round 8
// speedup vs baseline: 2.9165x; 1.0004x over previous
#include <cuda_runtime.h>

// Fixed problem shape (GNNReachabilityNet): N=100000 nodes, E=1600000 edges, G=64 graphs.
#define NMAX  100352
#define GMAX  64

struct Params {
    float p1[11], q1[11], p2[11], q2[11];
    float ps, qs, s0, b2, bo;
};

__device__ Params   gP;
__device__ float    g_alpha[NMAX];   // alpha = x.p2
__device__ float2   g_bg[NMAX];      // (beta = x.q2, gamma = x.p1)
__device__ float    g_delta[NMAX];   // delta = x.q1
__device__ float2   g_agg[NMAX];     // (sum alpha over incoming, deg)
__device__ float    g_w[NMAX];       // w[u] = beta[u] + s[u]
__device__ float    g_aggs[NMAX];    // sum of w[src] over incoming
__device__ unsigned g_outmax[GMAX];  // order-encoded float max
__device__ unsigned g_done = 0;
__device__ int      g_flag;          // 1 = int64 indices, 0 = int32

__device__ __forceinline__ unsigned enc_f(float f) {
    unsigned u = __float_as_uint(f);
    return (u & 0x80000000u) ? ~u : (u | 0x80000000u);
}
__device__ __forceinline__ float dec_f(unsigned e) {
    return (e & 0x80000000u) ? __uint_as_float(e ^ 0x80000000u) : __uint_as_float(~e);
}
#define ENC_NEG_INF 0x007FFFFFu

// ---------------------------------------------------------------------------
// Shared 2-edge index loader (wide loads, int32 or int64).
// Returns s0,s1,d0,d1; d1 = -1 for a single trailing edge.
// ---------------------------------------------------------------------------
__device__ __forceinline__ void load2(const void* __restrict__ ei, int E, int e0,
                                      bool f64, int& s0, int& s1, int& d0, int& d1) {
    bool two = (e0 + 1 < E);
    if (f64) {
        const long long* p = (const long long*)ei;
        if (two) {
            longlong2 sv = *(const longlong2*)(p + e0);
            s0 = (int)sv.x; s1 = (int)sv.y;
            if ((E & 1) == 0) {
                longlong2 dv = *(const longlong2*)(p + E + e0);
                d0 = (int)dv.x; d1 = (int)dv.y;
            } else {
                d0 = (int)p[E + e0]; d1 = (int)p[E + e0 + 1];
            }
        } else {
            s0 = (int)p[e0]; d0 = (int)p[E + e0]; s1 = s0; d1 = -1;
        }
    } else {
        const int* p = (const int*)ei;
        if (two) {
            int2 sv = *(const int2*)(p + e0);
            s0 = sv.x; s1 = sv.y;
            if ((E & 1) == 0) {
                int2 dv = *(const int2*)(p + E + e0);
                d0 = dv.x; d1 = dv.y;
            } else {
                d0 = p[E + e0]; d1 = p[E + e0 + 1];
            }
        } else {
            s0 = p[e0]; d0 = p[E + e0]; s1 = s0; d1 = -1;
        }
    }
}

// ---------------------------------------------------------------------------
// K1: single-block weight fold via right-to-left matrix-vector products
// (~60k MACs). Also: dtype detect, init g_outmax / g_done.
// ---------------------------------------------------------------------------
__global__ void k_fold(const float* __restrict__ Wv,  const float* __restrict__ bv,
                       const float* __restrict__ We1, const float* __restrict__ be1,
                       const float* __restrict__ Wx,  const float* __restrict__ bx,
                       const float* __restrict__ We2, const float* __restrict__ be2,
                       const float* __restrict__ Wo,  const float* __restrict__ bo,
                       const unsigned* __restrict__ ei_words) {
    __shared__ float wev[64], wfv[64];
    __shared__ float uf[128], ue[128];
    __shared__ float taf[64], tae[64], tbf[64], tbe[64];
    const int tid = threadIdx.x;  // 256 threads

    if (tid == 0) {
        int nz = 0;
#pragma unroll
        for (int i = 0; i < 64; i++) nz += (ei_words[2 * i + 1] != 0u);
        g_flag = (nz == 0);
        g_done = 0u;
    }
    if (tid < GMAX) g_outmax[tid] = ENC_NEG_INF;

    // wev = We2[0:64]@Wo, wfv = We2[64:128]@Wo
    if (tid < 64) {
        float a = 0.f, b = 0.f;
        for (int o = 0; o < 64; o++) {
            float wo = Wo[o];
            a += We2[tid * 64 + o]        * wo;
            b += We2[(64 + tid) * 64 + o] * wo;
        }
        wev[tid] = a; wfv[tid] = b;
    }
    __syncthreads();
    // uf = Wx@wfv, ue = Wx@wev
    if (tid < 128) {
        float a = 0.f, b = 0.f;
        for (int o = 0; o < 64; o++) {
            float wx = Wx[tid * 64 + o];
            a += wx * wfv[o];
            b += wx * wev[o];
        }
        uf[tid] = a; ue[tid] = b;
    }
    __syncthreads();
    // taf = Wa@uf, tae = Wa@ue, tbf = Wb@uf, tbe = Wb@ue
    {
        int k = tid & 63, q = tid >> 6;
        const float* row = We1 + ((q < 2 ? k : 64 + k) * 128);
        const float* u = (q & 1) ? ue : uf;
        float a = 0.f;
        for (int m = 0; m < 128; m++) a += row[m] * u[m];
        if (q == 0) taf[k] = a;
        else if (q == 1) tae[k] = a;
        else if (q == 2) tbf[k] = a;
        else tbe[k] = a;
    }
    __syncthreads();
    // p/q 11-vectors (+ We1 rows 128..131 corrections for x cols 9,10)
    if (tid < 44) {
        int i = tid % 11, gq = tid / 11;  // 0=p1,1=q1,2=p2,3=q2
        const float* tv = (gq == 0) ? taf : (gq == 1) ? tae : (gq == 2) ? tbf : tbe;
        float a = 0.f;
        for (int k = 0; k < 64; k++) a += Wv[i * 64 + k] * tv[k];
        if (i >= 9) {
            int row = (gq < 2 ? 128 : 130) + (i - 9);
            const float* u = (gq & 1) ? ue : uf;
            const float* r = We1 + row * 128;
            float c = 0.f;
            for (int m = 0; m < 128; m++) c += r[m] * u[m];
            a += c;
        }
        if (gq == 0) gP.p1[i] = a;
        else if (gq == 1) gP.q1[i] = a;
        else if (gq == 2) gP.p2[i] = a;
        else gP.q2[i] = a;
    }
    if (tid == 64) {
        float s0 = 0.f, t0 = 0.f, b2 = 0.f;
        for (int o = 0; o < 64; o++) {
            s0 += bx[o]  * wfv[o];
            t0 += bx[o]  * wev[o];
            b2 += be2[o] * Wo[o];
        }
        float ps = s0, qs = t0;
        for (int m = 0; m < 128; m++) {
            ps += be1[m] * uf[m];
            qs += be1[m] * ue[m];
        }
        for (int k = 0; k < 64; k++) {
            ps += bv[k] * (taf[k] + tbf[k]);
            qs += bv[k] * (tae[k] + tbe[k]);
        }
        gP.ps = ps; gP.qs = qs; gP.s0 = s0;
        gP.b2 = b2 + bo[0]; gP.bo = bo[0];
    }
}

// ---------------------------------------------------------------------------
// K2: per-node 11-dim dots (x staged via smem float4); zero accumulators.
// ---------------------------------------------------------------------------
__global__ void __launch_bounds__(256) k_dots(const float* __restrict__ x, int n) {
    __shared__ float sx[256 * 11];
    __shared__ float sp1[11], sq1[11], sp2[11], sq2[11];
    int t = threadIdx.x;
    if (t < 11) {
        sp1[t] = gP.p1[t]; sq1[t] = gP.q1[t];
        sp2[t] = gP.p2[t]; sq2[t] = gP.q2[t];
    }
    int base = blockIdx.x * 2816;
    int lim = n * 11 - base;
    if (lim >= 2816) {
        const float4* xv = (const float4*)(x + base);
        float4* s4 = (float4*)sx;
        s4[t]       = xv[t];
        s4[t + 256] = xv[t + 256];
        if (t + 512 < 704) s4[t + 512] = xv[t + 512];
    } else {
        for (int j = t; j < 2816; j += 256)
            sx[j] = (j < lim) ? x[base + j] : 0.f;
    }
    __syncthreads();
    int v = blockIdx.x * 256 + t;
    if (v < n) {
        float a = 0.f, b = 0.f, g = 0.f, d = 0.f;
#pragma unroll
        for (int i = 0; i < 11; i++) {
            float xv = sx[t * 11 + i];
            a += xv * sp2[i]; b += xv * sq2[i];
            g += xv * sp1[i]; d += xv * sq1[i];
        }
        g_alpha[v] = a;
        g_bg[v]    = make_float2(b, g);
        g_delta[v] = d;
        g_agg[v]   = make_float2(0.f, 0.f);
        g_aggs[v]  = 0.f;
    }
}

// ---------------------------------------------------------------------------
// K3: edge pass 1 — 2 edges/thread: wide index loads, gather alpha,
// float2 RED (sum_alpha, deg). No index-cache write.
// ---------------------------------------------------------------------------
__global__ void __launch_bounds__(256) k_edge1(const void* __restrict__ ei, int E) {
    int i = blockIdx.x * 256 + threadIdx.x;
    int e0 = 2 * i;
    if (e0 >= E) return;
    int s0, s1, d0, d1;
    load2(ei, E, e0, g_flag != 0, s0, s1, d0, d1);

    float a0 = __ldg(&g_alpha[s0]);
    if (d1 >= 0) {
        float a1 = __ldg(&g_alpha[s1]);
        if (d0 == d1) {
            atomicAdd(&g_agg[d0], make_float2(a0 + a1, 2.f));
        } else {
            atomicAdd(&g_agg[d0], make_float2(a0, 1.f));
            atomicAdd(&g_agg[d1], make_float2(a1, 1.f));
        }
    } else {
        atomicAdd(&g_agg[d0], make_float2(a0, 1.f));
    }
}

// ---------------------------------------------------------------------------
// K4: per-node w = beta + s.
// ---------------------------------------------------------------------------
__global__ void __launch_bounds__(256) k_nodes(int n) {
    int v = blockIdx.x * 256 + threadIdx.x;
    if (v >= n) return;
    float2 ag = g_agg[v];
    float2 bg = g_bg[v];
    float s = (ag.y > 0.f) ? (bg.y + (1.f / ag.y) * ag.x + gP.ps) : gP.s0;
    g_w[v] = bg.x + s;
}

// ---------------------------------------------------------------------------
// K5: edge pass 2 — 2 edges/thread re-reading edge_index (L2-hot):
// gather w, scalar RED: aggs[dst] += w[src].
// ---------------------------------------------------------------------------
__global__ void __launch_bounds__(256) k_edge2(const void* __restrict__ ei, int E) {
    int i = blockIdx.x * 256 + threadIdx.x;
    int e0 = 2 * i;
    if (e0 >= E) return;
    int s0, s1, d0, d1;
    load2(ei, E, e0, g_flag != 0, s0, s1, d0, d1);

    float w0 = __ldg(&g_w[s0]);
    if (d1 >= 0) {
        float w1 = __ldg(&g_w[s1]);
        if (d0 == d1) {
            atomicAdd(&g_aggs[d0], w0 + w1);
        } else {
            atomicAdd(&g_aggs[d0], w0);
            atomicAdd(&g_aggs[d1], w1);
        }
    } else {
        atomicAdd(&g_aggs[d0], w0);
    }
}

// ---------------------------------------------------------------------------
// K6: node_out + segment max + last-block writeout.
// ---------------------------------------------------------------------------
__global__ void __launch_bounds__(256) k_final(const void* __restrict__ batch,
                                               float* out, int n, int out_n) {
    __shared__ unsigned smax[GMAX];
    __shared__ int s_done;
    int t = threadIdx.x;
    if (t < GMAX) smax[t] = ENC_NEG_INF;
    __syncthreads();

    const bool f64 = (g_flag != 0);
    float qb = gP.qs + gP.b2, bo_ = gP.bo;
    int v = blockIdx.x * 256 + t;
    if (v < n) {
        float deg = g_agg[v].y;
        float no = (deg > 0.f)
                 ? (g_delta[v] + qb + (1.f / deg) * g_aggs[v])
                 : bo_;
        int g = f64 ? (int)((const long long*)batch)[v]
                    : ((const int*)batch)[v];
        atomicMax(&smax[g], enc_f(no));
    }
    __syncthreads();
    if (t < GMAX && smax[t] != ENC_NEG_INF)
        atomicMax(&g_outmax[t], smax[t]);
    __syncthreads();
    if (t == 0) {
        __threadfence();
        s_done = (atomicAdd(&g_done, 1u) == gridDim.x - 1u);
    }
    __syncthreads();
    if (s_done && t < GMAX && t < out_n) {
        unsigned vmax = atomicAdd(&g_outmax[t], 0u);  // coherent L2 read
        out[t] = dec_f(vmax);
    }
}

extern "C" void kernel_launch(void* const* d_in, const int* in_sizes, int n_in,
                              void* d_out, int out_size) {
    const float* x     = (const float*)d_in[0];
    const void*  ei    = d_in[1];
    const void*  batch = d_in[2];
    const float* Wv  = (const float*)d_in[3];
    const float* bv  = (const float*)d_in[4];
    const float* We1 = (const float*)d_in[5];
    const float* be1 = (const float*)d_in[6];
    const float* Wx  = (const float*)d_in[7];
    const float* bx  = (const float*)d_in[8];
    const float* We2 = (const float*)d_in[9];
    const float* be2 = (const float*)d_in[10];
    const float* Wo  = (const float*)d_in[11];
    const float* bo  = (const float*)d_in[12];
    float* out = (float*)d_out;

    int n = in_sizes[0] / 11;   // 100000
    int E = in_sizes[1] / 2;    // 1600000
    if (n > NMAX) n = NMAX;

    const int TPB = 256;
    int nb_n = (n + TPB - 1) / TPB;
    int nb_e = ((E + 1) / 2 + TPB - 1) / TPB;

    k_fold<<<1, 256>>>(Wv, bv, We1, be1, Wx, bx, We2, be2, Wo, bo,
                       (const unsigned*)ei);
    k_dots<<<nb_n, TPB>>>(x, n);
    k_edge1<<<nb_e, TPB>>>(ei, E);
    k_nodes<<<nb_n, TPB>>>(n);
    k_edge2<<<nb_e, TPB>>>(ei, E);
    k_final<<<nb_n, TPB>>>(batch, out, n, out_size);
}

// round 9
// speedup vs baseline: 3.0463x; 1.0445x over previous
#include <cuda_runtime.h>

// Fixed problem shape (GNNReachabilityNet): N=100000 nodes, E=1600000 edges, G=64 graphs.
#define NMAX  100352
#define GMAX  64
#define EMAXH 800000   // max edge pairs (E/2)

struct Params {
    float p1[11], q1[11], p2[11], q2[11];
    float ps, qs, s0, b2, bo;
};

__device__ Params   gP;
__device__ float    g_alpha[NMAX];   // alpha = x.p2
__device__ float2   g_bg[NMAX];      // (beta = x.q2, gamma = x.p1)
__device__ float    g_delta[NMAX];   // delta = x.q1
__device__ float2   g_agg[NMAX];     // (sum alpha over incoming, deg)
__device__ float    g_w[NMAX];       // w[u] = beta[u] + s[u]
__device__ float    g_aggs[NMAX];    // sum of w[src] over incoming
__device__ int4     g_eidx[EMAXH];   // packed (s0,d0,s1,d1) per edge pair
__device__ unsigned g_outmax[GMAX];  // order-encoded float max
__device__ unsigned g_done = 0;
__device__ int      g_flag;          // 1 = int64 indices, 0 = int32

__device__ __forceinline__ unsigned enc_f(float f) {
    unsigned u = __float_as_uint(f);
    return (u & 0x80000000u) ? ~u : (u | 0x80000000u);
}
__device__ __forceinline__ float dec_f(unsigned e) {
    return (e & 0x80000000u) ? __uint_as_float(e ^ 0x80000000u) : __uint_as_float(~e);
}
#define ENC_NEG_INF 0x007FFFFFu

// ---------------------------------------------------------------------------
// K1: weight fold, R3-style COALESCED loops (m = idx % width varies across
// adjacent threads), fp32. Also: dtype detect, init g_outmax / g_done.
// ---------------------------------------------------------------------------
__global__ void k_fold(const float* __restrict__ Wv,  const float* __restrict__ bv,
                       const float* __restrict__ We1, const float* __restrict__ be1,
                       const float* __restrict__ Wx,  const float* __restrict__ bx,
                       const float* __restrict__ We2, const float* __restrict__ be2,
                       const float* __restrict__ Wo,  const float* __restrict__ bo,
                       const unsigned* __restrict__ ei_words) {
    __shared__ float M1[11 * 128], M2[11 * 128];
    __shared__ float A1[11 * 64],  A2[11 * 64];
    __shared__ float c1[128], c2[64], wev[64], wfv[64];
    const int t = threadIdx.x;  // 256 threads

    if (t == 0) {
        // int64 little-endian nonneg < 2^31 => odd 32-bit words all zero.
        int nz = 0;
#pragma unroll
        for (int i = 0; i < 64; i++) nz += (ei_words[2 * i + 1] != 0u);
        g_flag = (nz == 0);
        g_done = 0u;
    }
    if (t < GMAX) g_outmax[t] = ENC_NEG_INF;

    // M1 = Wv@Wa + Pc, M2 = Wv@Wb + Pd  (coalesced over m)
    for (int idx = t; idx < 11 * 128; idx += 256) {
        int i = idx / 128, m = idx % 128;
        float a1 = 0.f, a2 = 0.f;
        for (int k = 0; k < 64; k++) {
            float wk = Wv[i * 64 + k];
            a1 += wk * We1[k * 128 + m];
            a2 += wk * We1[(64 + k) * 128 + m];
        }
        if (i == 9)  { a1 += We1[128 * 128 + m]; a2 += We1[130 * 128 + m]; }
        if (i == 10) { a1 += We1[129 * 128 + m]; a2 += We1[131 * 128 + m]; }
        M1[idx] = a1; M2[idx] = a2;
    }
    for (int m = t; m < 128; m += 256) {
        float c = be1[m];
        for (int k = 0; k < 64; k++)
            c += bv[k] * (We1[k * 128 + m] + We1[(64 + k) * 128 + m]);
        c1[m] = c;
    }
    for (int j = t; j < 64; j += 256) {
        float a = 0.f, b = 0.f;
        for (int o = 0; o < 64; o++) {
            a += We2[j * 64 + o]        * Wo[o];
            b += We2[(64 + j) * 64 + o] * Wo[o];
        }
        wev[j] = a; wfv[j] = b;
    }
    __syncthreads();
    // A1 = M1@Wx, A2 = M2@Wx  (coalesced over o)
    for (int idx = t; idx < 11 * 64; idx += 256) {
        int i = idx / 64, o = idx % 64;
        float a1 = 0.f, a2 = 0.f;
        for (int m = 0; m < 128; m++) {
            float wx = Wx[m * 64 + o];
            a1 += M1[i * 128 + m] * wx;
            a2 += M2[i * 128 + m] * wx;
        }
        A1[idx] = a1; A2[idx] = a2;
    }
    for (int o = t; o < 64; o += 256) {
        float c = bx[o];
        for (int m = 0; m < 128; m++) c += c1[m] * Wx[m * 64 + o];
        c2[o] = c;
    }
    __syncthreads();
    if (t < 11) {
        int i = t;
        float a = 0.f, b = 0.f, g = 0.f, d = 0.f;
        for (int o = 0; o < 64; o++) {
            a += A2[i * 64 + o] * wfv[o]; // p2 -> alpha
            b += A2[i * 64 + o] * wev[o]; // q2 -> beta
            g += A1[i * 64 + o] * wfv[o]; // p1 -> gamma
            d += A1[i * 64 + o] * wev[o]; // q1 -> delta
        }
        gP.p2[i] = a; gP.q2[i] = b;
        gP.p1[i] = g; gP.q1[i] = d;
    }
    if (t == 32) {
        float ps = 0.f, qs = 0.f, s0 = 0.f, b2 = 0.f;
        for (int o = 0; o < 64; o++) {
            ps += c2[o] * wfv[o];
            qs += c2[o] * wev[o];
            s0 += bx[o] * wfv[o];
            b2 += be2[o] * Wo[o];
        }
        gP.ps = ps; gP.qs = qs; gP.s0 = s0;
        gP.b2 = b2 + bo[0]; gP.bo = bo[0];
    }
}

// ---------------------------------------------------------------------------
// K2: per-node 11-dim dots (x staged via smem float4); zero accumulators.
// ---------------------------------------------------------------------------
__global__ void __launch_bounds__(256) k_dots(const float* __restrict__ x, int n) {
    __shared__ float sx[256 * 11];
    __shared__ float sp1[11], sq1[11], sp2[11], sq2[11];
    int t = threadIdx.x;
    if (t < 11) {
        sp1[t] = gP.p1[t]; sq1[t] = gP.q1[t];
        sp2[t] = gP.p2[t]; sq2[t] = gP.q2[t];
    }
    int base = blockIdx.x * 2816;
    int lim = n * 11 - base;
    if (lim >= 2816) {
        const float4* xv = (const float4*)(x + base);
        float4* s4 = (float4*)sx;
        s4[t]       = xv[t];
        s4[t + 256] = xv[t + 256];
        if (t + 512 < 704) s4[t + 512] = xv[t + 512];
    } else {
        for (int j = t; j < 2816; j += 256)
            sx[j] = (j < lim) ? x[base + j] : 0.f;
    }
    __syncthreads();
    int v = blockIdx.x * 256 + t;
    if (v < n) {
        float a = 0.f, b = 0.f, g = 0.f, d = 0.f;
#pragma unroll
        for (int i = 0; i < 11; i++) {
            float xv = sx[t * 11 + i];
            a += xv * sp2[i]; b += xv * sq2[i];
            g += xv * sp1[i]; d += xv * sq1[i];
        }
        g_alpha[v] = a;
        g_bg[v]    = make_float2(b, g);
        g_delta[v] = d;
        g_agg[v]   = make_float2(0.f, 0.f);
        g_aggs[v]  = 0.f;
    }
}

// ---------------------------------------------------------------------------
// K3: edge pass 1 — 2 edges/thread: wide index loads, write packed int32
// pairs for pass 2, gather alpha (4B), float2 RED (sum_alpha, deg).
// ---------------------------------------------------------------------------
__global__ void __launch_bounds__(256) k_edge1(const void* __restrict__ ei, int E) {
    int i = blockIdx.x * 256 + threadIdx.x;
    int e0 = 2 * i;
    if (e0 >= E) return;
    const bool f64 = (g_flag != 0);
    int s0, s1, d0, d1;
    bool two = (e0 + 1 < E);
    if (f64) {
        const long long* p = (const long long*)ei;
        if (two) {
            longlong2 sv = *(const longlong2*)(p + e0);
            s0 = (int)sv.x; s1 = (int)sv.y;
            if ((E & 1) == 0) {
                longlong2 dv = *(const longlong2*)(p + E + e0);
                d0 = (int)dv.x; d1 = (int)dv.y;
            } else {
                d0 = (int)p[E + e0]; d1 = (int)p[E + e0 + 1];
            }
        } else {
            s0 = (int)p[e0]; d0 = (int)p[E + e0]; s1 = s0; d1 = -1;
        }
    } else {
        const int* p = (const int*)ei;
        if (two) {
            int2 sv = *(const int2*)(p + e0);
            s0 = sv.x; s1 = sv.y;
            if ((E & 1) == 0) {
                int2 dv = *(const int2*)(p + E + e0);
                d0 = dv.x; d1 = dv.y;
            } else {
                d0 = p[E + e0]; d1 = p[E + e0 + 1];
            }
        } else {
            s0 = p[e0]; d0 = p[E + e0]; s1 = s0; d1 = -1;
        }
    }
    g_eidx[i] = make_int4(s0, d0, s1, d1);

    float a0 = __ldg(&g_alpha[s0]);
    if (d1 >= 0) {
        float a1 = __ldg(&g_alpha[s1]);
        if (d0 == d1) {
            atomicAdd(&g_agg[d0], make_float2(a0 + a1, 2.f));
        } else {
            atomicAdd(&g_agg[d0], make_float2(a0, 1.f));
            atomicAdd(&g_agg[d1], make_float2(a1, 1.f));
        }
    } else {
        atomicAdd(&g_agg[d0], make_float2(a0, 1.f));
    }
}

// ---------------------------------------------------------------------------
// K4: per-node w = beta + s.
// ---------------------------------------------------------------------------
__global__ void __launch_bounds__(256) k_nodes(int n) {
    int v = blockIdx.x * 256 + threadIdx.x;
    if (v >= n) return;
    float2 ag = g_agg[v];
    float2 bg = g_bg[v];
    float s = (ag.y > 0.f) ? (bg.y + (1.f / ag.y) * ag.x + gP.ps) : gP.s0;
    g_w[v] = bg.x + s;
}

// ---------------------------------------------------------------------------
// K5: edge pass 2 — 2 edges/thread from packed int32 pairs (L2-resident):
// gather w, scalar RED: aggs[dst] += w[src].
// ---------------------------------------------------------------------------
__global__ void __launch_bounds__(256) k_edge2(int E) {
    int i = blockIdx.x * 256 + threadIdx.x;
    if (2 * i >= E) return;
    int4 p = g_eidx[i];
    float w0 = __ldg(&g_w[p.x]);
    if (p.w >= 0) {
        float w1 = __ldg(&g_w[p.z]);
        if (p.y == p.w) {
            atomicAdd(&g_aggs[p.y], w0 + w1);
        } else {
            atomicAdd(&g_aggs[p.y], w0);
            atomicAdd(&g_aggs[p.w], w1);
        }
    } else {
        atomicAdd(&g_aggs[p.y], w0);
    }
}

// ---------------------------------------------------------------------------
// K6: node_out + segment max + last-block writeout.
// ---------------------------------------------------------------------------
__global__ void __launch_bounds__(256) k_final(const void* __restrict__ batch,
                                               float* out, int n, int out_n) {
    __shared__ unsigned smax[GMAX];
    __shared__ int s_done;
    int t = threadIdx.x;
    if (t < GMAX) smax[t] = ENC_NEG_INF;
    __syncthreads();

    const bool f64 = (g_flag != 0);
    float qb = gP.qs + gP.b2, bo_ = gP.bo;
    int v = blockIdx.x * 256 + t;
    if (v < n) {
        float deg = g_agg[v].y;
        float no = (deg > 0.f)
                 ? (g_delta[v] + qb + (1.f / deg) * g_aggs[v])
                 : bo_;
        int g = f64 ? (int)((const long long*)batch)[v]
                    : ((const int*)batch)[v];
        atomicMax(&smax[g], enc_f(no));
    }
    __syncthreads();
    if (t < GMAX && smax[t] != ENC_NEG_INF)
        atomicMax(&g_outmax[t], smax[t]);
    __syncthreads();
    if (t == 0) {
        __threadfence();
        s_done = (atomicAdd(&g_done, 1u) == gridDim.x - 1u);
    }
    __syncthreads();
    if (s_done && t < GMAX && t < out_n) {
        unsigned vmax = atomicAdd(&g_outmax[t], 0u);  // coherent L2 read
        out[t] = dec_f(vmax);
    }
}

extern "C" void kernel_launch(void* const* d_in, const int* in_sizes, int n_in,
                              void* d_out, int out_size) {
    const float* x     = (const float*)d_in[0];
    const void*  ei    = d_in[1];
    const void*  batch = d_in[2];
    const float* Wv  = (const float*)d_in[3];
    const float* bv  = (const float*)d_in[4];
    const float* We1 = (const float*)d_in[5];
    const float* be1 = (const float*)d_in[6];
    const float* Wx  = (const float*)d_in[7];
    const float* bx  = (const float*)d_in[8];
    const float* We2 = (const float*)d_in[9];
    const float* be2 = (const float*)d_in[10];
    const float* Wo  = (const float*)d_in[11];
    const float* bo  = (const float*)d_in[12];
    float* out = (float*)d_out;

    int n = in_sizes[0] / 11;   // 100000
    int E = in_sizes[1] / 2;    // 1600000
    if (n > NMAX) n = NMAX;
    if (E > 2 * EMAXH) E = 2 * EMAXH;

    const int TPB = 256;
    int nb_n = (n + TPB - 1) / TPB;
    int nb_e = ((E + 1) / 2 + TPB - 1) / TPB;

    k_fold<<<1, 256>>>(Wv, bv, We1, be1, Wx, bx, We2, be2, Wo, bo,
                       (const unsigned*)ei);
    k_dots<<<nb_n, TPB>>>(x, n);
    k_edge1<<<nb_e, TPB>>>(ei, E);
    k_nodes<<<nb_n, TPB>>>(n);
    k_edge2<<<nb_e, TPB>>>(E);
    k_final<<<nb_n, TPB>>>(batch, out, n, out_size);
}